// round 2
// baseline (speedup 1.0000x reference)
#include <cuda_runtime.h>
#include <cstdint>

#define N_NODES 50000
#define N_EDGES 1600000
#define IN_DIM 64
#define HD 64
#define NUM_HEADS 4
#define OUT_DIM 16

// ---------------- device scratch ----------------
__device__ float g_Q[N_NODES * HD];
__device__ float g_K[N_NODES * HD];
__device__ float g_V[N_NODES * HD];
__device__ float g_Z[N_NODES * NUM_HEADS];

// ---------------- helpers ----------------
__device__ __forceinline__ void red_add_v4(float* p, float a, float b, float c, float d) {
    asm volatile("red.global.add.v4.f32 [%0], {%1,%2,%3,%4};"
                 :: "l"(p), "f"(a), "f"(b), "f"(c), "f"(d) : "memory");
}
__device__ __forceinline__ void fma2(uint64_t& d, uint64_t a, uint64_t b) {
    asm("fma.rn.f32x2 %0, %1, %2, %0;" : "+l"(d) : "l"(a), "l"(b));
}
__device__ __forceinline__ float hsum2(uint64_t v) {
    float2 f = *reinterpret_cast<float2*>(&v);
    return f.x + f.y;
}

// Tile GEMM half: computes, for this thread, 8 rows x 4 dims
// (dims = dg*8 + 4*h .. +3), accumulating packed over c-pairs.
// tile: [128 rows x stride 68] row-major floats in smem.
// w2  : packed/permuted weights: w2[cp*64 + (dim&7)*8 + (dim>>3)] = (W[2cp][dim], W[2cp+1][dim])
__device__ __forceinline__ void gemm_half(const float* __restrict__ tile,
                                          const uint64_t* __restrict__ w2,
                                          int eg, int dg, int h,
                                          float out[8][4], const float* __restrict__ b_s) {
    uint64_t acc[8][4];
#pragma unroll
    for (int i = 0; i < 8; i++)
#pragma unroll
        for (int j = 0; j < 4; j++) acc[i][j] = 0ull;

    const uint64_t* arow[8];
#pragma unroll
    for (int i = 0; i < 8; i++)
        arow[i] = reinterpret_cast<const uint64_t*>(tile + (eg * 8 + i) * 68);

    const uint64_t* wp = w2 + h * 32 + dg;  // (jj=4h+j) -> jj*8+dg = h*32 + j*8 + dg

#pragma unroll 4
    for (int cp = 0; cp < 32; cp++) {
        uint64_t w[4];
#pragma unroll
        for (int j = 0; j < 4; j++) w[j] = wp[cp * 64 + j * 8];
        uint64_t a[8];
#pragma unroll
        for (int i = 0; i < 8; i++) a[i] = arow[i][cp];
#pragma unroll
        for (int i = 0; i < 8; i++)
#pragma unroll
            for (int j = 0; j < 4; j++) fma2(acc[i][j], a[i], w[j]);
    }

    float bb[4];
#pragma unroll
    for (int j = 0; j < 4; j++) bb[j] = b_s[dg * 8 + h * 4 + j];
#pragma unroll
    for (int i = 0; i < 8; i++)
#pragma unroll
        for (int j = 0; j < 4; j++) out[i][j] = hsum2(acc[i][j]) + bb[j];
}

// Cooperative loaders (128 threads)
__device__ __forceinline__ void load_tile_rows(float* __restrict__ dst,
                                               const float* __restrict__ src,
                                               int base, int nrows_clamp, int tid) {
    for (int f = tid; f < 128 * 16; f += 128) {
        int r = f >> 4, q = f & 15;
        int gr = base + r;
        if (gr >= nrows_clamp) gr = nrows_clamp - 1;
        float4 v = reinterpret_cast<const float4*>(src + (size_t)gr * 64)[q];
        float* d = dst + r * 68 + q * 4;
        reinterpret_cast<float4*>(d)[0] = v;
    }
}
__device__ __forceinline__ void build_w2(uint64_t* __restrict__ w2,
                                         const float* __restrict__ W, int tid) {
    for (int idx = tid; idx < 2048; idx += 128) {
        int cp = idx >> 6, d = idx & 63;
        float lo = W[(2 * cp) * 64 + d];
        float hi = W[(2 * cp + 1) * 64 + d];
        float2 p = make_float2(lo, hi);
        w2[cp * 64 + (d & 7) * 8 + (d >> 3)] = *reinterpret_cast<uint64_t*>(&p);
    }
}

// ---------------- zero init ----------------
__global__ void zero_kernel(float* __restrict__ out) {
    int i = blockIdx.x * blockDim.x + threadIdx.x;
    if (i < N_NODES * HD) out[i] = 0.0f;
    if (i < N_NODES * NUM_HEADS) g_Z[i] = 0.0f;
}

// ---------------- node projections ----------------
#define PROJ_SMEM_FLOATS (128 * 68 + 4096 + 64)
__global__ __launch_bounds__(128)
void proj_kernel(const float* __restrict__ x,
                 const float* __restrict__ WQ, const float* __restrict__ bQ,
                 const float* __restrict__ WK, const float* __restrict__ bK,
                 const float* __restrict__ WV, const float* __restrict__ bV) {
    const float* W; const float* b; float* out;
    if (blockIdx.y == 0)      { W = WQ; b = bQ; out = g_Q; }
    else if (blockIdx.y == 1) { W = WK; b = bK; out = g_K; }
    else                      { W = WV; b = bV; out = g_V; }

    extern __shared__ float sm[];
    float* x_s = sm;                                       // 128*68
    uint64_t* w2 = reinterpret_cast<uint64_t*>(sm + 128 * 68);  // 2048 u64
    float* b_s = sm + 128 * 68 + 4096;                     // 64

    const int tid = threadIdx.x;
    const int base = blockIdx.x * 128;

    build_w2(w2, W, tid);
    if (tid < 64) b_s[tid] = b[tid];
    load_tile_rows(x_s, x, base, N_NODES, tid);
    __syncthreads();

    const int eg = tid >> 3, dg = tid & 7;
#pragma unroll
    for (int h = 0; h < 2; h++) {
        float r[8][4];
        gemm_half(x_s, w2, eg, dg, h, r, b_s);
#pragma unroll
        for (int i = 0; i < 8; i++) {
            int n = base + eg * 8 + i;
            if (n < N_NODES) {
                float4 o = make_float4(r[i][0], r[i][1], r[i][2], r[i][3]);
                *reinterpret_cast<float4*>(out + (size_t)n * 64 + dg * 8 + h * 4) = o;
            }
        }
    }
}

// ---------------- fused edge kernel ----------------
#define EDGE_SMEM_FLOATS (128 * 68 + 128 * 68 + 4096 + 64 + 256)
__global__ __launch_bounds__(128)
void edge_kernel(const float* __restrict__ ea,
                 const int* __restrict__ eidx,
                 const float* __restrict__ WE, const float* __restrict__ bE,
                 float* __restrict__ out) {
    extern __shared__ float sm[];
    float* ea_s = sm;                                           // 128*68
    float* E_s  = sm + 128 * 68;                                // 128*68
    uint64_t* w2 = reinterpret_cast<uint64_t*>(sm + 2 * 128 * 68);  // 2048 u64
    float* b_s  = sm + 2 * 128 * 68 + 4096;                     // 64
    int* si_s   = reinterpret_cast<int*>(b_s + 64);             // 128
    int* di_s   = si_s + 128;                                   // 128

    const int tid = threadIdx.x;
    const int base = blockIdx.x * 128;

    build_w2(w2, WE, tid);
    if (tid < 64) b_s[tid] = bE[tid];
    if (tid < 128) {
        si_s[tid] = eidx[base + tid];
        di_s[tid] = eidx[N_EDGES + base + tid];
    }
    load_tile_rows(ea_s, ea, base, N_EDGES, tid);
    __syncthreads();

    // ---- Phase A: E = ea @ WE + bE (packed f32x2 GEMM) ----
    const int eg = tid >> 3, dg = tid & 7;
#pragma unroll
    for (int h = 0; h < 2; h++) {
        float r[8][4];
        gemm_half(ea_s, w2, eg, dg, h, r, b_s);
#pragma unroll
        for (int i = 0; i < 8; i++) {
            float4 o = make_float4(r[i][0], r[i][1], r[i][2], r[i][3]);
            *reinterpret_cast<float4*>(E_s + (eg * 8 + i) * 68 + dg * 8 + h * 4) = o;
        }
    }
    __syncthreads();

    // ---- Phase B: per (edge, head): score + scatter ----
#pragma unroll
    for (int pass = 0; pass < 4; pass++) {
        const int le = pass * 32 + (tid >> 2);
        const int h  = tid & 3;
        const int src = si_s[le];
        const int dst = di_s[le];

        const float4* Kp = reinterpret_cast<const float4*>(g_K + (size_t)src * 64 + h * 16);
        const float4* Qp = reinterpret_cast<const float4*>(g_Q + (size_t)dst * 64 + h * 16);
        const float4* Ep = reinterpret_cast<const float4*>(E_s + le * 68 + h * 16);

        float s = 0.0f;
#pragma unroll
        for (int q = 0; q < 4; q++) {
            float4 k = Kp[q];
            float4 qv = Qp[q];
            float4 e = Ep[q];
            s += k.x * qv.x * e.x + k.y * qv.y * e.y + k.z * qv.z * e.z + k.w * qv.w * e.w;
        }
        s *= 0.25f;  // 1/sqrt(16)
        s = fminf(fmaxf(s, -5.0f), 5.0f);
        s = __expf(s);

        const float4* Vp = reinterpret_cast<const float4*>(g_V + (size_t)src * 64 + h * 16);
        float* ob = out + (size_t)dst * 64 + h * 16;
#pragma unroll
        for (int q = 0; q < 4; q++) {
            float4 v = Vp[q];
            red_add_v4(ob + q * 4, v.x * s, v.y * s, v.z * s, v.w * s);
        }
        atomicAdd(g_Z + (size_t)dst * 4 + h, s);
    }
}

// ---------------- finalize ----------------
__global__ void finalize_kernel(float* __restrict__ out) {
    int i = blockIdx.x * blockDim.x + threadIdx.x;
    if (i < N_NODES * HD) {
        int n = i >> 6;
        int h = (i >> 4) & 3;
        out[i] = out[i] / (g_Z[n * 4 + h] + 1e-6f);
    }
}

// ---------------- launch ----------------
extern "C" void kernel_launch(void* const* d_in, const int* in_sizes, int n_in,
                              void* d_out, int out_size) {
    const float* x   = (const float*)d_in[0];
    const float* ea  = (const float*)d_in[1];
    const int*   ei  = (const int*)  d_in[2];
    const float* WQ  = (const float*)d_in[3];
    const float* bQ  = (const float*)d_in[4];
    const float* WK  = (const float*)d_in[5];
    const float* bK  = (const float*)d_in[6];
    const float* WE  = (const float*)d_in[7];
    const float* bE  = (const float*)d_in[8];
    const float* WV  = (const float*)d_in[9];
    const float* bV  = (const float*)d_in[10];
    float* out = (float*)d_out;

    static_assert(EDGE_SMEM_FLOATS * 4 < 227 * 1024, "smem");
    cudaFuncSetAttribute(edge_kernel, cudaFuncAttributeMaxDynamicSharedMemorySize,
                         EDGE_SMEM_FLOATS * (int)sizeof(float));
    cudaFuncSetAttribute(proj_kernel, cudaFuncAttributeMaxDynamicSharedMemorySize,
                         PROJ_SMEM_FLOATS * (int)sizeof(float));

    {
        int total = N_NODES * HD;
        zero_kernel<<<(total + 255) / 256, 256>>>(out);
    }
    {
        dim3 grid((N_NODES + 127) / 128, 3);
        proj_kernel<<<grid, 128, PROJ_SMEM_FLOATS * sizeof(float)>>>(x, WQ, bQ, WK, bK, WV, bV);
    }
    {
        edge_kernel<<<N_EDGES / 128, 128, EDGE_SMEM_FLOATS * sizeof(float)>>>(ea, ei, WE, bE, out);
    }
    {
        int total = N_NODES * HD;
        finalize_kernel<<<(total + 255) / 256, 256>>>(out);
    }
}

// round 3
// speedup vs baseline: 1.8593x; 1.8593x over previous
#include <cuda_runtime.h>
#include <cstdint>

#define N_NODES 50000
#define N_EDGES 1600000
#define IN_DIM 64
#define HD 64
#define NUM_HEADS 4
#define OUT_DIM 16

// ---------------- device scratch ----------------
__device__ float g_Q[N_NODES * HD];
__device__ float g_K[N_NODES * HD];
__device__ float g_V[N_NODES * HD];
__device__ float g_Z[N_NODES * NUM_HEADS];

// ---------------- helpers ----------------
__device__ __forceinline__ void red_add_v4(float* p, float a, float b, float c, float d) {
    asm volatile("red.global.add.v4.f32 [%0], {%1,%2,%3,%4};"
                 :: "l"(p), "f"(a), "f"(b), "f"(c), "f"(d) : "memory");
}

// ---------------- zero init ----------------
__global__ void zero_kernel(float* __restrict__ out) {
    int i = blockIdx.x * blockDim.x + threadIdx.x;
    if (i < N_NODES * HD) out[i] = 0.0f;
    if (i < N_NODES * NUM_HEADS) g_Z[i] = 0.0f;
}

// ---------------- node projections: out = x @ W + b ----------------
// Tile: 128 nodes x 64 dims, 128 threads, 8x8 micro-tile per thread (scalar FFMA).
#define PROJ_SMEM_FLOATS (128 * 65 + 64 * 64 + 64)
__global__ __launch_bounds__(128)
void proj_kernel(const float* __restrict__ x,
                 const float* __restrict__ WQ, const float* __restrict__ bQ,
                 const float* __restrict__ WK, const float* __restrict__ bK,
                 const float* __restrict__ WV, const float* __restrict__ bV) {
    const float* W; const float* b; float* out;
    if (blockIdx.y == 0)      { W = WQ; b = bQ; out = g_Q; }
    else if (blockIdx.y == 1) { W = WK; b = bK; out = g_K; }
    else                      { W = WV; b = bV; out = g_V; }

    extern __shared__ float sm[];
    float* x_s = sm;                 // 128 * 65
    float* w_s = sm + 128 * 65;      // 64 * 64
    float* b_s = w_s + 64 * 64;      // 64

    const int tid = threadIdx.x;
    const int base = blockIdx.x * 128;

    {
        const float4* W4 = reinterpret_cast<const float4*>(W);
        float4* ws4 = reinterpret_cast<float4*>(w_s);
        #pragma unroll
        for (int i = tid; i < 1024; i += 128) ws4[i] = W4[i];
    }
    if (tid < 64) b_s[tid] = b[tid];

    for (int f = tid; f < 128 * 16; f += 128) {
        int r = f >> 4, q = f & 15;
        int gr = base + r;
        if (gr >= N_NODES) gr = N_NODES - 1;
        float4 v = reinterpret_cast<const float4*>(x + (size_t)gr * 64)[q];
        float* d = x_s + r * 65 + q * 4;
        d[0] = v.x; d[1] = v.y; d[2] = v.z; d[3] = v.w;
    }
    __syncthreads();

    const int eg = tid >> 3, dg = tid & 7;

    float acc[8][8];
    #pragma unroll
    for (int i = 0; i < 8; i++)
        #pragma unroll
        for (int j = 0; j < 8; j++) acc[i][j] = 0.0f;

    const float4* ws4 = reinterpret_cast<const float4*>(w_s);
    #pragma unroll 4
    for (int c = 0; c < 64; c++) {
        float4 w0 = ws4[c * 16 + dg * 2];
        float4 w1 = ws4[c * 16 + dg * 2 + 1];
        float a[8];
        #pragma unroll
        for (int i = 0; i < 8; i++) a[i] = x_s[(eg * 8 + i) * 65 + c];
        #pragma unroll
        for (int i = 0; i < 8; i++) {
            acc[i][0] += a[i] * w0.x; acc[i][1] += a[i] * w0.y;
            acc[i][2] += a[i] * w0.z; acc[i][3] += a[i] * w0.w;
            acc[i][4] += a[i] * w1.x; acc[i][5] += a[i] * w1.y;
            acc[i][6] += a[i] * w1.z; acc[i][7] += a[i] * w1.w;
        }
    }

    float bb[8];
    #pragma unroll
    for (int j = 0; j < 8; j++) bb[j] = b_s[dg * 8 + j];
    #pragma unroll
    for (int i = 0; i < 8; i++) {
        int n = base + eg * 8 + i;
        if (n < N_NODES) {
            float4 o0 = make_float4(acc[i][0] + bb[0], acc[i][1] + bb[1], acc[i][2] + bb[2], acc[i][3] + bb[3]);
            float4 o1 = make_float4(acc[i][4] + bb[4], acc[i][5] + bb[5], acc[i][6] + bb[6], acc[i][7] + bb[7]);
            float4* dst = reinterpret_cast<float4*>(out + (size_t)n * 64 + dg * 8);
            dst[0] = o0; dst[1] = o1;
        }
    }
}

// ---------------- fused edge kernel (register epilogue, single sync) ----------------
// Thread (eg,dg) computes E for 8 edges x 8 dims (one half of head h=dg>>1), then
// immediately does score (pair-reduce via shfl_xor 1) + scatter, E never hits smem.
#define EDGE_SMEM_FLOATS (128 * 65 + 64 * 64 + 64 + 256)
__global__ __launch_bounds__(128)
void edge_kernel(const float* __restrict__ ea,
                 const int* __restrict__ eidx,
                 const float* __restrict__ WE, const float* __restrict__ bE,
                 float* __restrict__ out) {
    extern __shared__ float sm[];
    float* ea_s = sm;                               // 128 * 65
    float* w_s  = sm + 128 * 65;                    // 64 * 64
    float* b_s  = w_s + 64 * 64;                    // 64
    int* si_s   = reinterpret_cast<int*>(b_s + 64); // 128
    int* di_s   = si_s + 128;                       // 128

    const int tid = threadIdx.x;
    const int base = blockIdx.x * 128;

    {
        const float4* W4 = reinterpret_cast<const float4*>(WE);
        float4* ws4 = reinterpret_cast<float4*>(w_s);
        #pragma unroll
        for (int i = tid; i < 1024; i += 128) ws4[i] = W4[i];
    }
    if (tid < 64) b_s[tid] = bE[tid];
    si_s[tid] = eidx[base + tid];
    di_s[tid] = eidx[N_EDGES + base + tid];

    for (int f = tid; f < 128 * 16; f += 128) {
        int e = f >> 4, q = f & 15;
        float4 v = reinterpret_cast<const float4*>(ea + (size_t)(base + e) * 64)[q];
        float* d = ea_s + e * 65 + q * 4;
        d[0] = v.x; d[1] = v.y; d[2] = v.z; d[3] = v.w;
    }
    __syncthreads();

    const int eg = tid >> 3, dg = tid & 7;
    const int h = dg >> 1;

    // ---- GEMM: acc[i][j] = (ea_tile @ WE)[edge eg*8+i][dim dg*8+j] ----
    float acc[8][8];
    #pragma unroll
    for (int i = 0; i < 8; i++)
        #pragma unroll
        for (int j = 0; j < 8; j++) acc[i][j] = 0.0f;

    const float4* ws4 = reinterpret_cast<const float4*>(w_s);
    #pragma unroll 4
    for (int c = 0; c < 64; c++) {
        float4 w0 = ws4[c * 16 + dg * 2];
        float4 w1 = ws4[c * 16 + dg * 2 + 1];
        float a[8];
        #pragma unroll
        for (int i = 0; i < 8; i++) a[i] = ea_s[(eg * 8 + i) * 65 + c];
        #pragma unroll
        for (int i = 0; i < 8; i++) {
            acc[i][0] += a[i] * w0.x; acc[i][1] += a[i] * w0.y;
            acc[i][2] += a[i] * w0.z; acc[i][3] += a[i] * w0.w;
            acc[i][4] += a[i] * w1.x; acc[i][5] += a[i] * w1.y;
            acc[i][6] += a[i] * w1.z; acc[i][7] += a[i] * w1.w;
        }
    }

    float bb[8];
    #pragma unroll
    for (int j = 0; j < 8; j++) bb[j] = b_s[dg * 8 + j];

    // ---- Epilogue: per local edge, score + scatter directly from registers ----
    #pragma unroll
    for (int i = 0; i < 8; i++) {
        const int le = eg * 8 + i;
        const int src = si_s[le];
        const int dst = di_s[le];

        const float4* Kp = reinterpret_cast<const float4*>(g_K + (size_t)src * 64 + dg * 8);
        const float4* Qp = reinterpret_cast<const float4*>(g_Q + (size_t)dst * 64 + dg * 8);
        float4 k0 = Kp[0], k1 = Kp[1];
        float4 q0 = Qp[0], q1 = Qp[1];

        float p =
            k0.x * q0.x * (acc[i][0] + bb[0]) + k0.y * q0.y * (acc[i][1] + bb[1]) +
            k0.z * q0.z * (acc[i][2] + bb[2]) + k0.w * q0.w * (acc[i][3] + bb[3]) +
            k1.x * q1.x * (acc[i][4] + bb[4]) + k1.y * q1.y * (acc[i][5] + bb[5]) +
            k1.z * q1.z * (acc[i][6] + bb[6]) + k1.w * q1.w * (acc[i][7] + bb[7]);

        p += __shfl_xor_sync(0xffffffffu, p, 1);   // pair (dg even, dg odd) = full head
        float s = __expf(fminf(fmaxf(p * 0.25f, -5.0f), 5.0f));

        const float4* Vp = reinterpret_cast<const float4*>(g_V + (size_t)src * 64 + dg * 8);
        float4 v0 = Vp[0], v1 = Vp[1];
        float* ob = out + (size_t)dst * 64 + dg * 8;
        red_add_v4(ob,     v0.x * s, v0.y * s, v0.z * s, v0.w * s);
        red_add_v4(ob + 4, v1.x * s, v1.y * s, v1.z * s, v1.w * s);
        if ((dg & 1) == 0)
            atomicAdd(g_Z + (size_t)dst * 4 + h, s);
    }
}

// ---------------- finalize ----------------
__global__ void finalize_kernel(float* __restrict__ out) {
    int i = blockIdx.x * blockDim.x + threadIdx.x;
    if (i < N_NODES * HD) {
        int n = i >> 6;
        int h = (i >> 4) & 3;
        out[i] = out[i] / (g_Z[n * 4 + h] + 1e-6f);
    }
}

// ---------------- launch ----------------
extern "C" void kernel_launch(void* const* d_in, const int* in_sizes, int n_in,
                              void* d_out, int out_size) {
    const float* x   = (const float*)d_in[0];
    const float* ea  = (const float*)d_in[1];
    const int*   ei  = (const int*)  d_in[2];
    const float* WQ  = (const float*)d_in[3];
    const float* bQ  = (const float*)d_in[4];
    const float* WK  = (const float*)d_in[5];
    const float* bK  = (const float*)d_in[6];
    const float* WE  = (const float*)d_in[7];
    const float* bE  = (const float*)d_in[8];
    const float* WV  = (const float*)d_in[9];
    const float* bV  = (const float*)d_in[10];
    float* out = (float*)d_out;

    static_assert(EDGE_SMEM_FLOATS * 4 < 227 * 1024, "smem");
    cudaFuncSetAttribute(edge_kernel, cudaFuncAttributeMaxDynamicSharedMemorySize,
                         EDGE_SMEM_FLOATS * (int)sizeof(float));
    cudaFuncSetAttribute(proj_kernel, cudaFuncAttributeMaxDynamicSharedMemorySize,
                         PROJ_SMEM_FLOATS * (int)sizeof(float));

    {
        int total = N_NODES * HD;
        zero_kernel<<<(total + 255) / 256, 256>>>(out);
    }
    {
        dim3 grid((N_NODES + 127) / 128, 3);
        proj_kernel<<<grid, 128, PROJ_SMEM_FLOATS * sizeof(float)>>>(x, WQ, bQ, WK, bK, WV, bV);
    }
    {
        edge_kernel<<<N_EDGES / 128, 128, EDGE_SMEM_FLOATS * sizeof(float)>>>(ea, ei, WE, bE, out);
    }
    {
        int total = N_NODES * HD;
        finalize_kernel<<<(total + 255) / 256, 256>>>(out);
    }
}